// round 1
// baseline (speedup 1.0000x reference)
#include <cuda_runtime.h>

// Problem constants
// u, pregate, postgate: (4, 256, 128, 128) f32 ; k: (256, 64, 64) f32
// FFT size 256x256, rfft half-size 129. Output f32 (4,256,128,128).

#define N_IMG   1024          // B*C
#define N_CH    256
#define HH      128
#define WW      128
#define KH      64
#define KW      64
#define NF      256
#define NHF     129           // NF/2 + 1
#define COLG    17            // ceil(129/8)

// Scratch (device globals: allocation-free per harness rules)
__device__ float2 g_tmp[(size_t)N_IMG * HH * NHF];        // ~135 MB: row spectra / col-stage in-place
__device__ float2 g_kfrow[(size_t)N_CH * KH * NHF];       // ~17 MB : kernel row spectra
__device__ float2 g_kf[(size_t)N_CH * NHF * NF];          // ~68 MB : kernel 2D spectrum, [c][col][k]

__device__ __forceinline__ float2 cmul(float2 a, float2 b) {
    return make_float2(a.x * b.x - a.y * b.y, a.x * b.y + a.y * b.x);
}

// Radix-2 DIF Stockham FFT, N=256, NB batches in smem laid out [batch][256].
// x: input/output buffer, y: ping-pong scratch. Twiddles tw[k]=exp(-2*pi*i*k/256), k<128.
// 8 stages (even) -> result ends in x. Caller must __syncthreads() before calling.
template<int NB, int T>
__device__ __forceinline__ void fft256(float2* x, float2* y, const float2* tw, bool inv) {
    float2* a = x;
    float2* b = y;
#pragma unroll
    for (int st = 0; st < 8; st++) {
        const int s = 1 << st;
#pragma unroll
        for (int i = threadIdx.x; i < 128 * NB; i += T) {
            int f  = i & 127;
            int bt = i >> 7;
            int fb = f & ~(s - 1);
            float2 w = tw[fb];
            if (inv) w.y = -w.y;
            float2 u0 = a[bt * 256 + f];
            float2 u1 = a[bt * 256 + f + 128];
            float2 sm = make_float2(u0.x + u1.x, u0.y + u1.y);
            float2 df = make_float2(u0.x - u1.x, u0.y - u1.y);
            int o = f + fb;
            b[bt * 256 + o]     = sm;
            b[bt * 256 + o + s] = cmul(df, w);
        }
        __syncthreads();
        float2* t2 = a; a = b; b = t2;
    }
}

__device__ __forceinline__ void init_tw(float2* tw) {
    int t = threadIdx.x;
    if (t < 128) {
        float sn, cs;
        sincospif((float)t / 128.0f, &sn, &cs);
        tw[t] = make_float2(cs, -sn);
    }
}

// ---------------------------------------------------------------------------
// Kernel filter: row FFTs. One block per (channel, kernel-row). 128 threads.
__global__ void kf_rows_kernel(const float* __restrict__ kin) {
    __shared__ float2 A[256], B[256], tw[128];
    int blk = blockIdx.x;
    int c = blk >> 6;          // /64
    int r = blk & 63;
    int t = threadIdx.x;
    init_tw(tw);
    float v = (t < KW) ? kin[((size_t)c * KH + r) * KW + t] : 0.0f;
    A[t] = make_float2(v, 0.0f);
    A[t + 128] = make_float2(0.0f, 0.0f);
    __syncthreads();
    fft256<1, 128>(A, B, tw, false);
    float2* dst = g_kfrow + ((size_t)c * KH + r) * NHF;
    dst[t] = A[t];
    if (t == 0) dst[128] = A[128];
}

// Kernel filter: column FFTs (batched 8 cols). One block per (channel, colgroup). 256 threads.
__global__ void kf_cols_kernel() {
    __shared__ float2 A[8 * 256], B[8 * 256], tw[128];
    int blk = blockIdx.x;
    int c = blk / COLG;
    int col0 = (blk % COLG) * 8;
    int t = threadIdx.x;
    init_tw(tw);
    const float2* src = g_kfrow + (size_t)c * KH * NHF;
    for (int i = t; i < 8 * 256; i += 256) {
        int row = i >> 3;
        int cb  = i & 7;
        int col = col0 + cb;
        float2 v = make_float2(0.0f, 0.0f);
        if (row < KH && col < NHF) v = src[row * NHF + col];
        A[cb * 256 + row] = v;
    }
    __syncthreads();
    fft256<8, 256>(A, B, tw, false);
    // write [c][col][k], contiguous in k
    for (int i = t; i < 8 * 256; i += 256) {
        int cb = i >> 8;
        int k  = i & 255;
        int col = col0 + cb;
        if (col < NHF)
            g_kf[((size_t)c * NHF + col) * NF + k] = A[cb * 256 + k];
    }
}

// ---------------------------------------------------------------------------
// Forward row FFTs of u*pregate. One block per (image,row). 128 threads.
__global__ void fwd_rows_kernel(const float* __restrict__ u, const float* __restrict__ pre) {
    __shared__ float2 A[256], B[256], tw[128];
    int blk = blockIdx.x;
    int img = blk >> 7;
    int row = blk & 127;
    int t = threadIdx.x;
    init_tw(tw);
    size_t off = ((size_t)img * HH + row) * WW + t;
    A[t] = make_float2(u[off] * pre[off], 0.0f);
    A[t + 128] = make_float2(0.0f, 0.0f);
    __syncthreads();
    fft256<1, 128>(A, B, tw, false);
    float2* dst = g_tmp + ((size_t)img * HH + row) * NHF;
    dst[t] = A[t];
    if (t == 0) dst[128] = A[128];
}

// Column FFT + spectral multiply + inverse column FFT, 8 columns per block. 256 threads.
__global__ void conv_cols_kernel() {
    __shared__ float2 A[8 * 256], B[8 * 256], tw[128];
    int blk = blockIdx.x;
    int img = blk / COLG;
    int col0 = (blk % COLG) * 8;
    int c = img & 255;             // img = b*C + c
    int t = threadIdx.x;
    init_tw(tw);

    float2* base = g_tmp + (size_t)img * HH * NHF;
    // load 128 rows x 8 cols, zero-pad rows 128..255
    for (int i = t; i < 8 * 256; i += 256) {
        int row = i >> 3;
        int cb  = i & 7;
        int col = col0 + cb;
        float2 v = make_float2(0.0f, 0.0f);
        if (row < HH && col < NHF) v = base[row * NHF + col];
        A[cb * 256 + row] = v;
    }
    __syncthreads();
    fft256<8, 256>(A, B, tw, false);

    // multiply with kernel spectrum (contiguous k reads)
    const float2* kf = g_kf + ((size_t)c * NHF + col0) * NF;
    for (int i = t; i < 8 * 256; i += 256) {
        int cb = i >> 8;
        int k  = i & 255;
        if (col0 + cb < NHF) {
            float2 z = A[cb * 256 + k];
            A[cb * 256 + k] = cmul(z, kf[cb * 256 + k]);
        }
    }
    __syncthreads();
    fft256<8, 256>(A, B, tw, true);

    // write back first 128 rows (final crop keeps only these)
    for (int i = t; i < 8 * 128; i += 256) {
        int row = i >> 3;
        int cb  = i & 7;
        int col = col0 + cb;
        if (col < NHF) base[row * NHF + col] = A[cb * 256 + row];
    }
}

// Inverse row FFT (Hermitian reconstruction) + crop + scale + postgate. 128 threads.
__global__ void inv_rows_kernel(const float* __restrict__ post, float* __restrict__ out) {
    __shared__ float2 A[256], B[256], tw[128];
    int blk = blockIdx.x;
    int img = blk >> 7;
    int row = blk & 127;
    int t = threadIdx.x;
    init_tw(tw);
    const float2* src = g_tmp + ((size_t)img * HH + row) * NHF;
    float2 v = src[t];
    A[t] = v;
    if (t == 0) A[128] = src[128];
    else        A[256 - t] = make_float2(v.x, -v.y);
    __syncthreads();
    fft256<1, 128>(A, B, tw, true);
    const float scale = 1.0f / 65536.0f;   // 1/(256*256), applied once
    size_t off = ((size_t)img * HH + row) * WW + t;
    out[off] = A[t].x * scale * post[off];
}

// ---------------------------------------------------------------------------
extern "C" void kernel_launch(void* const* d_in, const int* in_sizes, int n_in,
                              void* d_out, int out_size) {
    const float* u    = (const float*)d_in[0];
    const float* k    = (const float*)d_in[1];
    const float* pre  = (const float*)d_in[2];
    const float* post = (const float*)d_in[3];
    float* out = (float*)d_out;

    kf_rows_kernel<<<N_CH * KH, 128>>>(k);
    kf_cols_kernel<<<N_CH * COLG, 256>>>();
    fwd_rows_kernel<<<N_IMG * HH, 128>>>(u, pre);
    conv_cols_kernel<<<N_IMG * COLG, 256>>>();
    inv_rows_kernel<<<N_IMG * HH, 128>>>(post, out);
}

// round 2
// speedup vs baseline: 2.1984x; 2.1984x over previous
#include <cuda_runtime.h>

// u, pregate, postgate: (4,256,128,128) f32 ; k: (256,64,64) f32
// y = postgate * irfft2( rfft2(u*pregate,256x256) * rfft2(k,256x256) )[:128,:128]

#define N_IMG   1024
#define N_CH    256
#define HH      128
#define WW      128
#define KH      64
#define KW      64
#define NF      256
#define NHF     129

// Scratch (device globals — allocation-free)
__device__ float2 g_tmp[(size_t)N_IMG * HH * NHF];     // row spectra / in-place col conv
__device__ float2 g_kfrow[(size_t)N_CH * KH * NHF];    // kernel row spectra
__device__ float2 g_kf[(size_t)N_CH * NHF * NF];       // kernel 2D spectrum [c][col][k]

__device__ __forceinline__ float2 cmul(float2 a, float2 b) {
    return make_float2(a.x * b.x - a.y * b.y, a.x * b.y + a.y * b.x);
}

// ---------------- FFT16 in registers, DIF radix-2, natural-order output ------
#define BF1(a,b) { float ax=a.x, ay=a.y; a.x=ax+b.x; a.y=ay+b.y; b.x=ax-b.x; b.y=ay-b.y; }
#define BFI(a,b) { float ax=a.x, ay=a.y; float dx=ax-b.x, dy=ay-b.y; a.x=ax+b.x; a.y=ay+b.y; b.x=dy; b.y=-dx; }
#define BFW(a,b,wr,wi) { float ax=a.x, ay=a.y; float dx=ax-b.x, dy=ay-b.y; \
    a.x=ax+b.x; a.y=ay+b.y; b.x=dx*(wr)-dy*(wi); b.y=dx*(wi)+dy*(wr); }
#define SW(a,b) { float2 _t=a; a=b; b=_t; }

__device__ __forceinline__ void fft16_n(float2 r[16]) {
    const float c1 = 0.92387953251128675613f;
    const float s1 = 0.38268343236508977173f;
    const float c2 = 0.70710678118654752440f;
    // stage 1 (half=8), twiddles W16^j
    BF1(r[0], r[8]);
    BFW(r[1], r[9],  c1, -s1);
    BFW(r[2], r[10], c2, -c2);
    BFW(r[3], r[11], s1, -c1);
    BFI(r[4], r[12]);
    BFW(r[5], r[13], -s1, -c1);
    BFW(r[6], r[14], -c2, -c2);
    BFW(r[7], r[15], -c1, -s1);
    // stage 2 (half=4), twiddles W8^j
    BF1(r[0], r[4]);  BFW(r[1], r[5],  c2, -c2); BFI(r[2], r[6]);  BFW(r[3], r[7],  -c2, -c2);
    BF1(r[8], r[12]); BFW(r[9], r[13], c2, -c2); BFI(r[10],r[14]); BFW(r[11],r[15], -c2, -c2);
    // stage 3 (half=2), twiddles {1,-i}
    BF1(r[0], r[2]);  BFI(r[1], r[3]);
    BF1(r[4], r[6]);  BFI(r[5], r[7]);
    BF1(r[8], r[10]); BFI(r[9], r[11]);
    BF1(r[12],r[14]); BFI(r[13],r[15]);
    // stage 4 (half=1)
    BF1(r[0], r[1]);  BF1(r[2], r[3]);  BF1(r[4], r[5]);  BF1(r[6], r[7]);
    BF1(r[8], r[9]);  BF1(r[10],r[11]); BF1(r[12],r[13]); BF1(r[14],r[15]);
    // un-bit-reverse
    SW(r[1], r[8]); SW(r[2], r[4]); SW(r[3], r[12]);
    SW(r[5], r[10]); SW(r[7], r[14]); SW(r[11], r[13]);
}

// 256-pt FFT, 2-pass 16x16. Thread t enters holding x[16*n1 + t] in r[n1],
// exits holding X[t + 16*k2] in r[k2]. Tb: this FFT's 272-float2 region.
// tw: smem table tw[i] = exp(-2*pi*i*i/256). All 256 threads must call.
__device__ __forceinline__ void fft256_2pass(float2 r[16], int t, float2* Tb,
                                             const float2* tw) {
    fft16_n(r);
    if (t) {
#pragma unroll
        for (int k1 = 1; k1 < 16; k1++) r[k1] = cmul(r[k1], tw[t * k1]);
    }
    __syncthreads();
#pragma unroll
    for (int k1 = 0; k1 < 16; k1++) Tb[k1 * 17 + t] = r[k1];
    __syncthreads();
#pragma unroll
    for (int n2 = 0; n2 < 16; n2++) r[n2] = Tb[t * 17 + n2];
    fft16_n(r);
}

__device__ __forceinline__ void init_tw256(float2* tw) {
    int i = threadIdx.x;   // blockDim = 256
    float sn, cs;
    sincospif((float)i / 128.0f, &sn, &cs);
    tw[i] = make_float2(cs, -sn);
}

// ---------------------------------------------------------------------------
// Kernel-filter row FFTs: 16 rows per block (one channel covers 4 blocks).
__global__ void kf_rows_kernel(const float* __restrict__ kin) {
    __shared__ float  Sf[16 * 129];
    __shared__ float2 T[16 * 272];
    __shared__ float2 tw[256];
    int blk = blockIdx.x;
    int c = blk >> 2, rg = blk & 3;
    int tid = threadIdx.x;
    init_tw256(tw);
    // load 16 rows x 64
    for (int i = tid; i < 1024; i += 256) {
        int rr = i >> 6, pos = i & 63;
        Sf[rr * 129 + pos] = kin[((size_t)c * KH + rg * 16 + rr) * KW + pos];
    }
    __syncthreads();
    int cb = tid >> 4, t = tid & 15;
    float2 r[16];
#pragma unroll
    for (int n1 = 0; n1 < 16; n1++) {
        int idx = 16 * n1 + t;
        r[n1] = (idx < KW) ? make_float2(Sf[cb * 129 + idx], 0.0f)
                           : make_float2(0.0f, 0.0f);
    }
    fft256_2pass(r, t, T + cb * 272, tw);
    int row = rg * 16 + cb;
    float2* dst = g_kfrow + ((size_t)c * KH + row) * NHF;
#pragma unroll
    for (int k2 = 0; k2 < 8; k2++) dst[t + 16 * k2] = r[k2];
    if (t == 0) dst[128] = r[8];
}

// Kernel-filter column FFTs: 16 columns per block, 9 groups per channel.
__global__ void kf_cols_kernel() {
    __shared__ float2 S[64 * 17];
    __shared__ float2 T[16 * 272];
    __shared__ float2 tw[256];
    int blk = blockIdx.x;
    int c = blk / 9, g = blk - c * 9;
    int col0 = g * 16;
    int tid = threadIdx.x;
    init_tw256(tw);
    const float2* src = g_kfrow + (size_t)c * KH * NHF;
    for (int i = tid; i < 1024; i += 256) {
        int row = i >> 4, cb = i & 15;
        int col = col0 + cb;
        S[row * 17 + cb] = (col < NHF) ? src[row * NHF + col]
                                       : make_float2(0.0f, 0.0f);
    }
    __syncthreads();
    int cb = tid >> 4, t = tid & 15;
    int col = col0 + cb;
    float2 r[16];
#pragma unroll
    for (int n1 = 0; n1 < 16; n1++) {
        int idx = 16 * n1 + t;
        r[n1] = (idx < KH) ? S[idx * 17 + cb] : make_float2(0.0f, 0.0f);
    }
    fft256_2pass(r, t, T + cb * 272, tw);
    if (col < NHF) {
        float2* dst = g_kf + ((size_t)c * NHF + col) * NF;
#pragma unroll
        for (int k2 = 0; k2 < 16; k2++) dst[t + 16 * k2] = r[k2];
    }
}

// ---------------------------------------------------------------------------
// Forward row FFTs of u*pregate: 16 rows per block.
__global__ void fwd_rows_kernel(const float* __restrict__ u,
                                const float* __restrict__ pre) {
    __shared__ float  Sf[16 * 129];
    __shared__ float2 T[16 * 272];
    __shared__ float2 tw[256];
    int blk = blockIdx.x;
    int img = blk >> 3, rg = blk & 7;
    int tid = threadIdx.x;
    init_tw256(tw);
    size_t ibase = ((size_t)img * HH + rg * 16) * WW;
    for (int i = tid; i < 2048; i += 256) {
        int rr = i >> 7, pos = i & 127;
        size_t off = ibase + (size_t)rr * WW + pos;
        Sf[rr * 129 + pos] = u[off] * pre[off];
    }
    __syncthreads();
    int cb = tid >> 4, t = tid & 15;
    float2 r[16];
#pragma unroll
    for (int n1 = 0; n1 < 16; n1++) {
        int idx = 16 * n1 + t;
        r[n1] = (idx < WW) ? make_float2(Sf[cb * 129 + idx], 0.0f)
                           : make_float2(0.0f, 0.0f);
    }
    fft256_2pass(r, t, T + cb * 272, tw);
    int row = rg * 16 + cb;
    float2* dst = g_tmp + ((size_t)img * HH + row) * NHF;
#pragma unroll
    for (int k2 = 0; k2 < 8; k2++) dst[t + 16 * k2] = r[k2];
    if (t == 0) dst[128] = r[8];
}

// Column FFT + spectral multiply + inverse column FFT, 16 columns per block.
__global__ void conv_cols_kernel() {
    __shared__ float2 S[128 * 17];
    __shared__ float2 T[16 * 272];
    __shared__ float2 tw[256];
    int blk = blockIdx.x;
    int img = blk / 9, g = blk - img * 9;
    int col0 = g * 16;
    int c = img & 255;
    int tid = threadIdx.x;
    init_tw256(tw);
    float2* base = g_tmp + (size_t)img * HH * NHF;
    for (int i = tid; i < 2048; i += 256) {
        int row = i >> 4, cb = i & 15;
        int col = col0 + cb;
        S[row * 17 + cb] = (col < NHF) ? base[row * NHF + col]
                                       : make_float2(0.0f, 0.0f);
    }
    __syncthreads();
    int cb = tid >> 4, t = tid & 15;
    int col = col0 + cb;
    float2 r[16];
#pragma unroll
    for (int n1 = 0; n1 < 16; n1++) {
        int idx = 16 * n1 + t;
        r[n1] = (idx < HH) ? S[idx * 17 + cb] : make_float2(0.0f, 0.0f);
    }
    // forward column FFT: thread t now holds U[t + 16*k2]
    fft256_2pass(r, t, T + cb * 272, tw);
    // spectral multiply (contiguous, coalesced per half-warp)
    if (col < NHF) {
        const float2* kfc = g_kf + ((size_t)c * NHF + col) * NF;
#pragma unroll
        for (int k2 = 0; k2 < 16; k2++) r[k2] = cmul(r[k2], kfc[t + 16 * k2]);
    }
    // inverse = conj -> forward -> conj  (layout already matches: r[k2] = Y[16*k2+t])
#pragma unroll
    for (int k2 = 0; k2 < 16; k2++) r[k2].y = -r[k2].y;
    fft256_2pass(r, t, T + cb * 272, tw);
    // keep rows 0..127 (thread t holds n = t + 16*m), conj, stage, coalesced store
#pragma unroll
    for (int m = 0; m < 8; m++) {
        int n = t + 16 * m;
        float2 v = r[m];
        v.y = -v.y;
        S[n * 17 + cb] = v;
    }
    __syncthreads();
    for (int i = tid; i < 2048; i += 256) {
        int row = i >> 4, cbb = i & 15;
        int cc = col0 + cbb;
        if (cc < NHF) base[row * NHF + cc] = S[row * 17 + cbb];
    }
}

// Inverse row FFTs (Hermitian) + crop + scale + postgate: 16 rows per block.
__global__ void inv_rows_kernel(const float* __restrict__ post,
                                float* __restrict__ out) {
    __shared__ float2 S[16 * 132];
    __shared__ float2 T[16 * 272];
    __shared__ float2 tw[256];
    int blk = blockIdx.x;
    int img = blk >> 3, rg = blk & 7;
    int tid = threadIdx.x;
    init_tw256(tw);
    int cb = tid >> 4, t = tid & 15;
    int row = rg * 16 + cb;
    const float2* src = g_tmp + ((size_t)img * HH + row) * NHF;
#pragma unroll
    for (int j = 0; j < 9; j++) {
        int idx = t + 16 * j;
        if (idx < NHF) S[cb * 132 + idx] = src[idx];
    }
    __syncthreads();
    float2 r[16];
#pragma unroll
    for (int n1 = 0; n1 < 16; n1++) {
        int idx = 16 * n1 + t;
        float2 v;
        if (idx <= 128) { v = S[cb * 132 + idx]; v.y = -v.y; }  // conj(Y)
        else            { v = S[cb * 132 + (256 - idx)]; }      // conj(conj(Y)) = stored
        r[n1] = v;
    }
    fft256_2pass(r, t, T + cb * 272, tw);
    const float scale = 1.0f / 65536.0f;   // 1/(256*256)
    size_t obase = ((size_t)img * HH + row) * WW;
#pragma unroll
    for (int m = 0; m < 8; m++) {
        int n = t + 16 * m;
        out[obase + n] = r[m].x * scale * post[obase + n];
    }
}

// ---------------------------------------------------------------------------
extern "C" void kernel_launch(void* const* d_in, const int* in_sizes, int n_in,
                              void* d_out, int out_size) {
    const float* u    = (const float*)d_in[0];
    const float* k    = (const float*)d_in[1];
    const float* pre  = (const float*)d_in[2];
    const float* post = (const float*)d_in[3];
    float* out = (float*)d_out;

    kf_rows_kernel<<<N_CH * 4, 256>>>(k);
    kf_cols_kernel<<<N_CH * 9, 256>>>();
    fwd_rows_kernel<<<N_IMG * 8, 256>>>(u, pre);
    conv_cols_kernel<<<N_IMG * 9, 256>>>();
    inv_rows_kernel<<<N_IMG * 8, 256>>>(post, out);
}

// round 3
// speedup vs baseline: 2.5659x; 1.1672x over previous
#include <cuda_runtime.h>

// u, pregate, postgate: (4,256,128,128) f32 ; k: (256,64,64) f32
// y = postgate * irfft2( rfft2(u*pregate,256x256) * rfft2(k,256x256) )[:128,:128]

#define N_IMG   1024
#define N_CH    256
#define HH      128
#define WW      128
#define KH      64
#define KW      64
#define NF      256
#define NHF     129

// kernel spectrum scratch
__device__ float2 g_kfrow[(size_t)N_CH * KH * NHF];
__device__ float2 g_kf[(size_t)N_CH * NHF * NF];    // [c][col][k], full 256 k

__device__ __forceinline__ float2 cmul(float2 a, float2 b) {
    return make_float2(a.x * b.x - a.y * b.y, a.x * b.y + a.y * b.x);
}
__device__ __forceinline__ float2 cmulc(float2 a, float wr, float wi) {
    return make_float2(a.x * wr - a.y * wi, a.x * wi + a.y * wr);
}

#define BF1(a,b) { float ax=a.x, ay=a.y; a.x=ax+b.x; a.y=ay+b.y; b.x=ax-b.x; b.y=ay-b.y; }
#define BFI(a,b) { float ax=a.x, ay=a.y; float dx=ax-b.x, dy=ay-b.y; a.x=ax+b.x; a.y=ay+b.y; b.x=dy; b.y=-dx; }
#define BFW(a,b,wr,wi) { float ax=a.x, ay=a.y; float dx=ax-b.x, dy=ay-b.y; \
    a.x=ax+b.x; a.y=ay+b.y; b.x=dx*(wr)-dy*(wi); b.y=dx*(wi)+dy*(wr); }
#define SW(a,b) { float2 _t=a; a=b; b=_t; }

#define C16_1 0.92387953251128675613f
#define S16_1 0.38268343236508977173f
#define RS2   0.70710678118654752440f

__device__ __forceinline__ void fft16_tail(float2 r[16]) {
    BF1(r[0], r[4]);  BFW(r[1], r[5],  RS2, -RS2); BFI(r[2], r[6]);  BFW(r[3], r[7],  -RS2, -RS2);
    BF1(r[8], r[12]); BFW(r[9], r[13], RS2, -RS2); BFI(r[10],r[14]); BFW(r[11],r[15], -RS2, -RS2);
    BF1(r[0], r[2]);  BFI(r[1], r[3]);
    BF1(r[4], r[6]);  BFI(r[5], r[7]);
    BF1(r[8], r[10]); BFI(r[9], r[11]);
    BF1(r[12],r[14]); BFI(r[13],r[15]);
    BF1(r[0], r[1]);  BF1(r[2], r[3]);  BF1(r[4], r[5]);  BF1(r[6], r[7]);
    BF1(r[8], r[9]);  BF1(r[10],r[11]); BF1(r[12],r[13]); BF1(r[14],r[15]);
    SW(r[1], r[8]); SW(r[2], r[4]); SW(r[3], r[12]);
    SW(r[5], r[10]); SW(r[7], r[14]); SW(r[11], r[13]);
}
__device__ __forceinline__ void fft16_n(float2 r[16]) {
    BF1(r[0], r[8]);
    BFW(r[1], r[9],  C16_1, -S16_1);
    BFW(r[2], r[10], RS2,   -RS2);
    BFW(r[3], r[11], S16_1, -C16_1);
    BFI(r[4], r[12]);
    BFW(r[5], r[13], -S16_1, -C16_1);
    BFW(r[6], r[14], -RS2,   -RS2);
    BFW(r[7], r[15], -C16_1, -S16_1);
    fft16_tail(r);
}
// first-stage pruned: inputs r[8..15] are implicitly zero
__device__ __forceinline__ void fft16_p(float2 r[16]) {
    r[8]  = r[0];
    r[9]  = cmulc(r[1],  C16_1, -S16_1);
    r[10] = cmulc(r[2],  RS2,   -RS2);
    r[11] = cmulc(r[3],  S16_1, -C16_1);
    r[12] = make_float2(r[4].y, -r[4].x);
    r[13] = cmulc(r[5], -S16_1, -C16_1);
    r[14] = cmulc(r[6], -RS2,   -RS2);
    r[15] = cmulc(r[7], -C16_1, -S16_1);
    fft16_tail(r);
}

// 256-pt FFT, 16x16 two-pass. Thread t enters with x[16*n1+t] in r[n1] (only
// r[0..7] needed if PRUNE), exits with X[t+16*k2] in r[k2]. Tb: 272-float2 slot.
template<bool PRUNE>
__device__ __forceinline__ void fft256_2pass(float2 r[16], int t, float2* Tb,
                                             const float2* tw) {
    if (PRUNE) fft16_p(r); else fft16_n(r);
    if (t) {
#pragma unroll
        for (int k1 = 1; k1 < 16; k1++) r[k1] = cmul(r[k1], tw[t * k1]);
    }
    __syncthreads();
#pragma unroll
    for (int k1 = 0; k1 < 16; k1++) Tb[k1 * 17 + t] = r[k1];
    __syncthreads();
#pragma unroll
    for (int n2 = 0; n2 < 16; n2++) r[n2] = Tb[t * 17 + n2];
    fft16_n(r);
}

__device__ __forceinline__ void init_tw256(float2* tw) {
    int i = threadIdx.x;
    if (i < 256) {
        float sn, cs;
        sincospif((float)i / 128.0f, &sn, &cs);
        tw[i] = make_float2(cs, -sn);
    }
}

__device__ __forceinline__ float2 shfl2(float2 v, int src, unsigned mask) {
    float2 r;
    r.x = __shfl_sync(mask, v.x, src, 32);
    r.y = __shfl_sync(mask, v.y, src, 32);
    return r;
}

// ---------------------------------------------------------------------------
// Kernel-filter row FFTs (as round 2): 16 rows per block.
__global__ void kf_rows_kernel(const float* __restrict__ kin) {
    __shared__ float  Sf[16 * 129];
    __shared__ float2 T[16 * 272];
    __shared__ float2 tw[256];
    int blk = blockIdx.x;
    int c = blk >> 2, rg = blk & 3;
    int tid = threadIdx.x;
    init_tw256(tw);
    for (int i = tid; i < 1024; i += 256) {
        int rr = i >> 6, pos = i & 63;
        Sf[rr * 129 + pos] = kin[((size_t)c * KH + rg * 16 + rr) * KW + pos];
    }
    __syncthreads();
    int cb = tid >> 4, t = tid & 15;
    float2 r[16];
#pragma unroll
    for (int n1 = 0; n1 < 8; n1++) {
        int idx = 16 * n1 + t;
        r[n1] = (idx < KW) ? make_float2(Sf[cb * 129 + idx], 0.0f)
                           : make_float2(0.0f, 0.0f);
    }
    fft256_2pass<true>(r, t, T + cb * 272, tw);
    int row = rg * 16 + cb;
    float2* dst = g_kfrow + ((size_t)c * KH + row) * NHF;
#pragma unroll
    for (int k2 = 0; k2 < 8; k2++) dst[t + 16 * k2] = r[k2];
    if (t == 0) dst[128] = r[8];
}

// Kernel-filter column FFTs (as round 2): 16 columns per block, 9 groups/channel.
__global__ void kf_cols_kernel() {
    __shared__ float2 S[64 * 17];
    __shared__ float2 T[16 * 272];
    __shared__ float2 tw[256];
    int blk = blockIdx.x;
    int c = blk / 9, g = blk - c * 9;
    int col0 = g * 16;
    int tid = threadIdx.x;
    init_tw256(tw);
    const float2* src = g_kfrow + (size_t)c * KH * NHF;
    for (int i = tid; i < 1024; i += 256) {
        int row = i >> 4, cb = i & 15;
        int col = col0 + cb;
        S[row * 17 + cb] = (col < NHF) ? src[row * NHF + col]
                                       : make_float2(0.0f, 0.0f);
    }
    __syncthreads();
    int cb = tid >> 4, t = tid & 15;
    int col = col0 + cb;
    float2 r[16];
#pragma unroll
    for (int n1 = 0; n1 < 8; n1++) {
        int idx = 16 * n1 + t;
        r[n1] = (idx < KH) ? S[idx * 17 + cb] : make_float2(0.0f, 0.0f);
    }
    fft256_2pass<true>(r, t, T + cb * 272, tw);
    if (col < NHF) {
        float2* dst = g_kf + ((size_t)c * NHF + col) * NF;
#pragma unroll
        for (int k2 = 0; k2 < 16; k2++) dst[t + 16 * k2] = r[k2];
    }
}

// ---------------------------------------------------------------------------
// Fused per-image kernel: 512 threads, smem-resident 128x129 spectrum.
// Smem layout (float2 units):
//   S    [0 .. 16512)          : 128 x 129 spectrum, pitch 129
//   pool [16512 .. 16512+8704) : FFT transpose slots (32 x 272), aliased with
//                                 phase-1 input staging and phase-2 col staging
//   tw   [25216 .. 25472)
#define SM_S     0
#define SM_POOL  16512
#define SM_TW    25216
#define SM_F2    25472
#define SMEM_BYTES (SM_F2 * 8)

__global__ __launch_bounds__(512)
void conv2d_fused_kernel(const float* __restrict__ u,
                         const float* __restrict__ pre,
                         const float* __restrict__ post,
                         float* __restrict__ out) {
    extern __shared__ float2 dyn[];
    float2* S    = dyn + SM_S;
    float2* pool = dyn + SM_POOL;
    float2* tw   = dyn + SM_TW;

    const int tid = threadIdx.x;
    const int img = blockIdx.x;
    const int c   = img & (N_CH - 1);
    const int cb  = tid >> 4;       // 0..31: FFT slot
    const int t   = tid & 15;       // lane within FFT
    const int lane = tid & 31;
    const int srcl = (lane & 16) | ((16 - t) & 15);   // Hermitian peer lane
    const size_t ibase = (size_t)img * (HH * WW);

    init_tw256(tw);
    float2* Tb = pool + cb * 272;

    // ---------------- Phase 1: forward row FFTs, row pairs packed ----------
    float* Zf = (float*)pool;   // [32 pairs][128] float2 interleaved
#pragma unroll 1
    for (int it = 0; it < 2; it++) {
        __syncthreads();   // pool reuse guard (also covers tw on first pass)
        int rbase = it * 64;
        for (int i = tid; i < 64 * 128; i += 512) {
            int rl = i >> 7, pos = i & 127;
            size_t off = ibase + (size_t)(rbase + rl) * WW + pos;
            Zf[(((rl >> 1) * 128) + pos) * 2 + (rl & 1)] = u[off] * pre[off];
        }
        __syncthreads();
        float2 r[16];
#pragma unroll
        for (int n1 = 0; n1 < 8; n1++)
            r[n1] = ((float2*)Zf)[cb * 128 + 16 * n1 + t];
        fft256_2pass<true>(r, t, Tb, tw);
        // separate packed spectra: A = row 2p, B = row 2p+1
        int p  = it * 32 + cb;
        int rA = 2 * p, rB = rA + 1;
#pragma unroll
        for (int k2 = 0; k2 <= 8; k2++) {
            float2 p1 = shfl2(r[(15 - k2) & 15], srcl, 0xffffffffu);
            float2 Zm = (t == 0) ? r[(16 - k2) & 15] : p1;
            Zm.y = -Zm.y;
            float2 Z = r[k2 & 15];
            float2 A = make_float2(0.5f * (Z.x + Zm.x), 0.5f * (Z.y + Zm.y));
            float2 d = make_float2(Z.x - Zm.x, Z.y - Zm.y);
            float2 B = make_float2(0.5f * d.y, -0.5f * d.x);
            int k = t + 16 * k2;
            if (k <= 128) {
                S[rA * 129 + k] = A;
                S[rB * 129 + k] = B;
            }
        }
    }

    // ---------------- Phase 2: column conv (129 cols as 128 slots) ---------
    float2* Scol = pool;   // [128][33]
#pragma unroll 1
    for (int g = 0; g < 4; g++) {
        __syncthreads();   // S writes done / pool reuse guard
        int col0 = g * 32;
        // stage columns into Scol (slot 0 of group 0 = packed cols {0,128})
        for (int i = tid; i < 128 * 32; i += 512) {
            int row = i >> 5, cb2 = i & 31;
            if (col0 == 0 && cb2 == 0)
                Scol[row * 33] = make_float2(S[row * 129].x, S[row * 129 + 128].x);
            else
                Scol[row * 33 + cb2] = S[row * 129 + col0 + cb2];
        }
        __syncthreads();
        float2 r[16];
#pragma unroll
        for (int n1 = 0; n1 < 8; n1++)
            r[n1] = Scol[(16 * n1 + t) * 33 + cb];
        fft256_2pass<true>(r, t, Tb, tw);   // forward column FFT

        int cidx = col0 + cb;
        if (cidx == 0) {
            // packed pair {0,128}: separate, multiply, recombine
            const float2* KA = g_kf + (size_t)c * NHF * NF;           // col 0
            const float2* KB = g_kf + ((size_t)c * NHF + 128) * NF;   // col 128
            float2 rn[16];
#pragma unroll
            for (int k2 = 0; k2 < 16; k2++) {
                float2 p1 = shfl2(r[15 - k2], srcl, 0x0000ffffu);
                float2 Zm = (t == 0) ? r[(16 - k2) & 15] : p1;
                Zm.y = -Zm.y;
                float2 Z = r[k2];
                float2 A = make_float2(0.5f * (Z.x + Zm.x), 0.5f * (Z.y + Zm.y));
                float2 d = make_float2(Z.x - Zm.x, Z.y - Zm.y);
                float2 B = make_float2(0.5f * d.y, -0.5f * d.x);
                int k = t + 16 * k2;
                float2 YA = cmul(A, KA[k]);
                float2 YB = cmul(B, KB[k]);
                rn[k2] = make_float2(YA.x - YB.y, YA.y + YB.x);
            }
#pragma unroll
            for (int k2 = 0; k2 < 16; k2++) r[k2] = rn[k2];
        } else {
            const float2* kfc = g_kf + ((size_t)c * NHF + cidx) * NF;
#pragma unroll
            for (int k2 = 0; k2 < 16; k2++)
                r[k2] = cmul(r[k2], kfc[t + 16 * k2]);
        }
        // inverse = conj -> fwd -> conj (1/N folded into final output scale)
#pragma unroll
        for (int k2 = 0; k2 < 16; k2++) r[k2].y = -r[k2].y;
        fft256_2pass<false>(r, t, Tb, tw);
        __syncthreads();   // all Tb reads done before overwriting pool
#pragma unroll
        for (int m = 0; m < 8; m++) {
            int n = t + 16 * m;
            Scol[n * 33 + cb] = make_float2(r[m].x, -r[m].y);
        }
        __syncthreads();
        for (int i = tid; i < 128 * 32; i += 512) {
            int row = i >> 5, cb2 = i & 31;
            if (col0 == 0 && cb2 == 0) {
                float2 v = Scol[row * 33];
                S[row * 129]       = make_float2(v.x, 0.0f);
                S[row * 129 + 128] = make_float2(v.y, 0.0f);
            } else {
                S[row * 129 + col0 + cb2] = Scol[row * 33 + cb2];
            }
        }
    }

    // ---------------- Phase 3: inverse row FFTs, row pairs packed ----------
    const float scale = 1.0f / 65536.0f;
#pragma unroll 1
    for (int it = 0; it < 2; it++) {
        __syncthreads();
        int p  = it * 32 + cb;
        int rA = 2 * p, rB = rA + 1;
        float2 r[16];
#pragma unroll
        for (int n1 = 0; n1 < 16; n1++) {
            int idx = 16 * n1 + t;
            float2 YA, YB;
            if (idx <= 128) {
                YA = S[rA * 129 + idx];
                YB = S[rB * 129 + idx];
            } else {
                int m2 = 256 - idx;
                float2 a = S[rA * 129 + m2];
                float2 b = S[rB * 129 + m2];
                YA = make_float2(a.x, -a.y);
                YB = make_float2(b.x, -b.y);
            }
            // r = conj(YA + i*YB)
            r[n1] = make_float2(YA.x - YB.y, -(YA.y + YB.x));
        }
        fft256_2pass<false>(r, t, Tb, tw);
        size_t oA = ibase + (size_t)rA * WW;
        size_t oB = oA + WW;
#pragma unroll
        for (int m = 0; m < 8; m++) {
            int n = t + 16 * m;
            out[oA + n] =  r[m].x * scale * post[oA + n];
            out[oB + n] = -r[m].y * scale * post[oB + n];
        }
    }
}

// ---------------------------------------------------------------------------
extern "C" void kernel_launch(void* const* d_in, const int* in_sizes, int n_in,
                              void* d_out, int out_size) {
    const float* u    = (const float*)d_in[0];
    const float* k    = (const float*)d_in[1];
    const float* pre  = (const float*)d_in[2];
    const float* post = (const float*)d_in[3];
    float* out = (float*)d_out;

    cudaFuncSetAttribute(conv2d_fused_kernel,
                         cudaFuncAttributeMaxDynamicSharedMemorySize, SMEM_BYTES);

    kf_rows_kernel<<<N_CH * 4, 256>>>(k);
    kf_cols_kernel<<<N_CH * 9, 256>>>();
    conv2d_fused_kernel<<<N_IMG, 512, SMEM_BYTES>>>(u, pre, post, out);
}

// round 4
// speedup vs baseline: 3.7127x; 1.4469x over previous
#include <cuda_runtime.h>

// u, pregate, postgate: (4,256,128,128) f32 ; k: (256,64,64) f32
// y = postgate * irfft2( rfft2(u*pregate,256x256) * rfft2(k,256x256) )[:128,:128]

#define N_IMG   1024
#define N_CH    256
#define HH      128
#define WW      128
#define KH      64
#define KW      64
#define NF      256
#define NHF     129

__device__ float2 g_kfrow[(size_t)N_CH * KH * NHF];
__device__ float2 g_kf[(size_t)N_CH * NHF * NF];    // [c][col][k]

__device__ __forceinline__ float2 cmul(float2 a, float2 b) {
    return make_float2(a.x * b.x - a.y * b.y, a.x * b.y + a.y * b.x);
}
__device__ __forceinline__ float2 cmulc(float2 a, float wr, float wi) {
    return make_float2(a.x * wr - a.y * wi, a.x * wi + a.y * wr);
}

#define BF1(a,b) { float ax=a.x, ay=a.y; a.x=ax+b.x; a.y=ay+b.y; b.x=ax-b.x; b.y=ay-b.y; }
#define BFI(a,b) { float ax=a.x, ay=a.y; float dx=ax-b.x, dy=ay-b.y; a.x=ax+b.x; a.y=ay+b.y; b.x=dy; b.y=-dx; }
#define BFW(a,b,wr,wi) { float ax=a.x, ay=a.y; float dx=ax-b.x, dy=ay-b.y; \
    a.x=ax+b.x; a.y=ay+b.y; b.x=dx*(wr)-dy*(wi); b.y=dx*(wi)+dy*(wr); }
#define SW(a,b) { float2 _t=a; a=b; b=_t; }
#define CADD(a,b) make_float2((a).x+(b).x, (a).y+(b).y)

#define C16_1 0.92387953251128675613f
#define S16_1 0.38268343236508977173f
#define RS2   0.70710678118654752440f

// stages 2-3 of DIF-16 (common)
__device__ __forceinline__ void fft16_stage23(float2 r[16]) {
    BF1(r[0], r[4]);  BFW(r[1], r[5],  RS2, -RS2); BFI(r[2], r[6]);  BFW(r[3], r[7],  -RS2, -RS2);
    BF1(r[8], r[12]); BFW(r[9], r[13], RS2, -RS2); BFI(r[10],r[14]); BFW(r[11],r[15], -RS2, -RS2);
    BF1(r[0], r[2]);  BFI(r[1], r[3]);
    BF1(r[4], r[6]);  BFI(r[5], r[7]);
    BF1(r[8], r[10]); BFI(r[9], r[11]);
    BF1(r[12],r[14]); BFI(r[13],r[15]);
}
__device__ __forceinline__ void fft16_last_full(float2 r[16]) {
    BF1(r[0], r[1]);  BF1(r[2], r[3]);  BF1(r[4], r[5]);  BF1(r[6], r[7]);
    BF1(r[8], r[9]);  BF1(r[10],r[11]); BF1(r[12],r[13]); BF1(r[14],r[15]);
    SW(r[1], r[8]); SW(r[2], r[4]); SW(r[3], r[12]);
    SW(r[5], r[10]); SW(r[7], r[14]); SW(r[11], r[13]);
}
// last stage, only natural outputs 0..7 (sums). X[bitrev3(j)] = r[2j]+r[2j+1].
__device__ __forceinline__ void fft16_last_half(float2 r[16]) {
    float2 s0 = CADD(r[0], r[1]);   // X0
    float2 s1 = CADD(r[2], r[3]);   // X4
    float2 s2 = CADD(r[4], r[5]);   // X2
    float2 s3 = CADD(r[6], r[7]);   // X6
    float2 s4 = CADD(r[8], r[9]);   // X1
    float2 s5 = CADD(r[10],r[11]);  // X5
    float2 s6 = CADD(r[12],r[13]);  // X3
    float2 s7 = CADD(r[14],r[15]);  // X7
    r[0]=s0; r[1]=s4; r[2]=s2; r[3]=s6; r[4]=s1; r[5]=s5; r[6]=s3; r[7]=s7;
}
__device__ __forceinline__ void fft16_stage1_full(float2 r[16]) {
    BF1(r[0], r[8]);
    BFW(r[1], r[9],  C16_1, -S16_1);
    BFW(r[2], r[10], RS2,   -RS2);
    BFW(r[3], r[11], S16_1, -C16_1);
    BFI(r[4], r[12]);
    BFW(r[5], r[13], -S16_1, -C16_1);
    BFW(r[6], r[14], -RS2,   -RS2);
    BFW(r[7], r[15], -C16_1, -S16_1);
}
// first stage with r[8..15] implicitly zero
__device__ __forceinline__ void fft16_stage1_prune(float2 r[16]) {
    r[8]  = r[0];
    r[9]  = cmulc(r[1],  C16_1, -S16_1);
    r[10] = cmulc(r[2],  RS2,   -RS2);
    r[11] = cmulc(r[3],  S16_1, -C16_1);
    r[12] = make_float2(r[4].y, -r[4].x);
    r[13] = cmulc(r[5], -S16_1, -C16_1);
    r[14] = cmulc(r[6], -RS2,   -RS2);
    r[15] = cmulc(r[7], -C16_1, -S16_1);
}

// 256-pt FFT, 16x16 two-pass, WARP-LOCAL sync only.
// Thread t enters with x[16*n1+t] in r[n1] (r[0..7] only if PRUNE),
// exits with X[t+16*k2] in r[k2] (k2<8 only if HALF).
template<bool PRUNE, bool HALF>
__device__ __forceinline__ void fft256_2pass(float2 r[16], int t, float2* Tb,
                                             const float2* tw) {
    if (PRUNE) fft16_stage1_prune(r); else fft16_stage1_full(r);
    fft16_stage23(r);
    fft16_last_full(r);
    if (t) {
#pragma unroll
        for (int k1 = 1; k1 < 16; k1++) r[k1] = cmul(r[k1], tw[t * k1]);
    }
    __syncwarp();                       // WAR guard vs previous use of Tb
#pragma unroll
    for (int k1 = 0; k1 < 16; k1++) Tb[k1 * 17 + t] = r[k1];
    __syncwarp();
#pragma unroll
    for (int n2 = 0; n2 < 16; n2++) r[n2] = Tb[t * 17 + n2];
    fft16_stage1_full(r);
    fft16_stage23(r);
    if (HALF) fft16_last_half(r); else fft16_last_full(r);
}

__device__ __forceinline__ void init_tw256(float2* tw) {
    int i = threadIdx.x;
    if (i < 256) {
        float sn, cs;
        sincospif((float)i / 128.0f, &sn, &cs);
        tw[i] = make_float2(cs, -sn);
    }
}

__device__ __forceinline__ float2 shfl2(float2 v, int src, unsigned mask) {
    float2 r;
    r.x = __shfl_sync(mask, v.x, src, 32);
    r.y = __shfl_sync(mask, v.y, src, 32);
    return r;
}

// ---------------------------------------------------------------------------
// Kernel-filter row FFTs: 16 rows per block.
__global__ void kf_rows_kernel(const float* __restrict__ kin) {
    __shared__ float  Sf[16 * 129];
    __shared__ float2 T[16 * 272];
    __shared__ float2 tw[256];
    int blk = blockIdx.x;
    int c = blk >> 2, rg = blk & 3;
    int tid = threadIdx.x;
    init_tw256(tw);
    for (int i = tid; i < 1024; i += 256) {
        int rr = i >> 6, pos = i & 63;
        Sf[rr * 129 + pos] = kin[((size_t)c * KH + rg * 16 + rr) * KW + pos];
    }
    __syncthreads();
    int cb = tid >> 4, t = tid & 15;
    float2 r[16];
#pragma unroll
    for (int n1 = 0; n1 < 8; n1++) {
        int idx = 16 * n1 + t;
        r[n1] = (idx < KW) ? make_float2(Sf[cb * 129 + idx], 0.0f)
                           : make_float2(0.0f, 0.0f);
    }
    fft256_2pass<true, false>(r, t, T + cb * 272, tw);
    int row = rg * 16 + cb;
    float2* dst = g_kfrow + ((size_t)c * KH + row) * NHF;
#pragma unroll
    for (int k2 = 0; k2 < 8; k2++) dst[t + 16 * k2] = r[k2];
    if (t == 0) dst[128] = r[8];
}

// Kernel-filter column FFTs: 16 columns per block, 9 groups/channel.
__global__ void kf_cols_kernel() {
    __shared__ float2 S[64 * 17];
    __shared__ float2 T[16 * 272];
    __shared__ float2 tw[256];
    int blk = blockIdx.x;
    int c = blk / 9, g = blk - c * 9;
    int col0 = g * 16;
    int tid = threadIdx.x;
    init_tw256(tw);
    const float2* src = g_kfrow + (size_t)c * KH * NHF;
    for (int i = tid; i < 1024; i += 256) {
        int row = i >> 4, cb = i & 15;
        int col = col0 + cb;
        S[row * 17 + cb] = (col < NHF) ? src[row * NHF + col]
                                       : make_float2(0.0f, 0.0f);
    }
    __syncthreads();
    int cb = tid >> 4, t = tid & 15;
    int col = col0 + cb;
    float2 r[16];
#pragma unroll
    for (int n1 = 0; n1 < 8; n1++) {
        int idx = 16 * n1 + t;
        r[n1] = (idx < KH) ? S[idx * 17 + cb] : make_float2(0.0f, 0.0f);
    }
    fft256_2pass<true, false>(r, t, T + cb * 272, tw);
    if (col < NHF) {
        float2* dst = g_kf + ((size_t)c * NHF + col) * NF;
#pragma unroll
        for (int k2 = 0; k2 < 16; k2++) dst[t + 16 * k2] = r[k2];
    }
}

// ---------------------------------------------------------------------------
// Fused per-image kernel. 512 threads. Only 3 block barriers total.
// Smem (float2): S[128*129] | pool[32*272] | tw[256]
#define SM_POOL  16512
#define SM_TW    25216
#define SM_F2    25472
#define SMEM_BYTES (SM_F2 * 8)

__global__ __launch_bounds__(512)
void conv2d_fused_kernel(const float* __restrict__ u,
                         const float* __restrict__ pre,
                         const float* __restrict__ post,
                         float* __restrict__ out) {
    extern __shared__ float2 dyn[];
    float2* S    = dyn;
    float2* pool = dyn + SM_POOL;
    float2* tw   = dyn + SM_TW;

    const int tid  = threadIdx.x;
    const int img  = blockIdx.x;
    const int c    = img & (N_CH - 1);
    const int cb   = tid >> 4;
    const int t    = tid & 15;
    const int lane = tid & 31;
    const int srcl = (lane & 16) | ((16 - t) & 15);
    const size_t ibase = (size_t)img * (HH * WW);

    init_tw256(tw);
    float2* Tb = pool + cb * 272;
    __syncthreads();   // tw ready

    // -------- Phase 1: forward row FFTs, row pairs packed (warp-private) ---
#pragma unroll 1
    for (int it = 0; it < 2; it++) {
        int p = it * 32 + cb;
        int rA = 2 * p, rB = rA + 1;
        const float* uA = u   + ibase + (size_t)rA * WW;
        const float* pA = pre + ibase + (size_t)rA * WW;
        float2 r[16];
#pragma unroll
        for (int n1 = 0; n1 < 8; n1++) {
            int idx = 16 * n1 + t;
            r[n1] = make_float2(uA[idx] * pA[idx],
                                uA[WW + idx] * pA[WW + idx]);
        }
        fft256_2pass<true, false>(r, t, Tb, tw);
        // separate packed spectra: A = row rA, B = row rB
#pragma unroll
        for (int k2 = 0; k2 <= 8; k2++) {
            float2 p1 = shfl2(r[(15 - k2) & 15], srcl, 0xffffffffu);
            float2 Zm = (t == 0) ? r[(16 - k2) & 15] : p1;
            Zm.y = -Zm.y;
            float2 Z = r[k2 & 15];
            float2 A = make_float2(0.5f * (Z.x + Zm.x), 0.5f * (Z.y + Zm.y));
            float2 d = make_float2(Z.x - Zm.x, Z.y - Zm.y);
            float2 B = make_float2(0.5f * d.y, -0.5f * d.x);
            int k = t + 16 * k2;
            if (k <= 128) {
                S[rA * 129 + k] = A;
                S[rB * 129 + k] = B;
            }
        }
    }
    __syncthreads();   // spectrum rows complete

    // -------- Phase 2: column conv, columns warp-private, no barriers ------
#pragma unroll 1
    for (int g = 0; g < 4; g++) {
        int cidx = g * 32 + cb;
        float2 r[16];
        if (cidx == 0) {   // packed pair {col 0, col 128} (both real-spectra)
#pragma unroll
            for (int n1 = 0; n1 < 8; n1++) {
                int row = 16 * n1 + t;
                r[n1] = make_float2(S[row * 129].x, S[row * 129 + 128].x);
            }
        } else {
#pragma unroll
            for (int n1 = 0; n1 < 8; n1++)
                r[n1] = S[(16 * n1 + t) * 129 + cidx];
        }
        fft256_2pass<true, false>(r, t, Tb, tw);

        if (cidx == 0) {
            const float2* KA = g_kf + (size_t)c * NHF * NF;
            const float2* KB = g_kf + ((size_t)c * NHF + 128) * NF;
            float2 rn[16];
#pragma unroll
            for (int k2 = 0; k2 < 16; k2++) {
                float2 p1 = shfl2(r[15 - k2], srcl, 0x0000ffffu);
                float2 Zm = (t == 0) ? r[(16 - k2) & 15] : p1;
                Zm.y = -Zm.y;
                float2 Z = r[k2];
                float2 A = make_float2(0.5f * (Z.x + Zm.x), 0.5f * (Z.y + Zm.y));
                float2 d = make_float2(Z.x - Zm.x, Z.y - Zm.y);
                float2 B = make_float2(0.5f * d.y, -0.5f * d.x);
                int k = t + 16 * k2;
                float2 YA = cmul(A, KA[k]);
                float2 YB = cmul(B, KB[k]);
                rn[k2] = make_float2(YA.x - YB.y, YA.y + YB.x);
            }
#pragma unroll
            for (int k2 = 0; k2 < 16; k2++) r[k2] = rn[k2];
        } else {
            const float2* kfc = g_kf + ((size_t)c * NHF + cidx) * NF;
#pragma unroll
            for (int k2 = 0; k2 < 16; k2++)
                r[k2] = cmul(r[k2], kfc[t + 16 * k2]);
        }
        // inverse = conj -> fwd(half-output) -> conj
#pragma unroll
        for (int k2 = 0; k2 < 16; k2++) r[k2].y = -r[k2].y;
        fft256_2pass<false, true>(r, t, Tb, tw);
        if (cidx == 0) {
#pragma unroll
            for (int m = 0; m < 8; m++) {
                int n = t + 16 * m;
                S[n * 129]       = make_float2(r[m].x, 0.0f);
                S[n * 129 + 128] = make_float2(-r[m].y, 0.0f);
            }
        } else {
#pragma unroll
            for (int m = 0; m < 8; m++) {
                int n = t + 16 * m;
                S[n * 129 + cidx] = make_float2(r[m].x, -r[m].y);
            }
        }
    }
    __syncthreads();   // all columns written

    // -------- Phase 3: inverse row FFTs, row pairs packed (warp-private) ---
    const float scale = 1.0f / 65536.0f;
#pragma unroll 1
    for (int it = 0; it < 2; it++) {
        int p = it * 32 + cb;
        int rA = 2 * p, rB = rA + 1;
        float2 r[16];
#pragma unroll
        for (int n1 = 0; n1 < 16; n1++) {
            int idx = 16 * n1 + t;
            float2 YA, YB;
            if (idx <= 128) {
                YA = S[rA * 129 + idx];
                YB = S[rB * 129 + idx];
            } else {
                int m2 = 256 - idx;
                float2 a = S[rA * 129 + m2];
                float2 b = S[rB * 129 + m2];
                YA = make_float2(a.x, -a.y);
                YB = make_float2(b.x, -b.y);
            }
            r[n1] = make_float2(YA.x - YB.y, -(YA.y + YB.x));
        }
        fft256_2pass<false, true>(r, t, Tb, tw);
        size_t oA = ibase + (size_t)rA * WW;
        size_t oB = oA + WW;
#pragma unroll
        for (int m = 0; m < 8; m++) {
            int n = t + 16 * m;
            out[oA + n] =  r[m].x * scale * post[oA + n];
            out[oB + n] = -r[m].y * scale * post[oB + n];
        }
    }
}

// ---------------------------------------------------------------------------
extern "C" void kernel_launch(void* const* d_in, const int* in_sizes, int n_in,
                              void* d_out, int out_size) {
    const float* u    = (const float*)d_in[0];
    const float* k    = (const float*)d_in[1];
    const float* pre  = (const float*)d_in[2];
    const float* post = (const float*)d_in[3];
    float* out = (float*)d_out;

    cudaFuncSetAttribute(conv2d_fused_kernel,
                         cudaFuncAttributeMaxDynamicSharedMemorySize, SMEM_BYTES);

    kf_rows_kernel<<<N_CH * 4, 256>>>(k);
    kf_cols_kernel<<<N_CH * 9, 256>>>();
    conv2d_fused_kernel<<<N_IMG, 512, SMEM_BYTES>>>(u, pre, post, out);
}

// round 5
// speedup vs baseline: 4.0543x; 1.0920x over previous
#include <cuda_runtime.h>

// u, pregate, postgate: (4,256,128,128) f32 ; k: (256,64,64) f32
// y = postgate * irfft2( rfft2(u*pregate,256x256) * rfft2(k,256x256) )[:128,:128]

#define N_IMG   1024
#define N_CH    256
#define HH      128
#define WW      128
#define KH      64
#define KW      64
#define NF      256
#define NHF     129

__device__ float2 g_kf[(size_t)N_CH * NHF * NF];    // [c][col][k]

__device__ __forceinline__ float2 cmul(float2 a, float2 b) {
    return make_float2(a.x * b.x - a.y * b.y, a.x * b.y + a.y * b.x);
}
__device__ __forceinline__ float2 cmulc(float2 a, float wr, float wi) {
    return make_float2(a.x * wr - a.y * wi, a.x * wi + a.y * wr);
}

#define BF1(a,b) { float ax=a.x, ay=a.y; a.x=ax+b.x; a.y=ay+b.y; b.x=ax-b.x; b.y=ay-b.y; }
#define BFI(a,b) { float ax=a.x, ay=a.y; float dx=ax-b.x, dy=ay-b.y; a.x=ax+b.x; a.y=ay+b.y; b.x=dy; b.y=-dx; }
#define BFW(a,b,wr,wi) { float ax=a.x, ay=a.y; float dx=ax-b.x, dy=ay-b.y; \
    a.x=ax+b.x; a.y=ay+b.y; b.x=dx*(wr)-dy*(wi); b.y=dx*(wi)+dy*(wr); }
#define SW(a,b) { float2 _t=a; a=b; b=_t; }
#define CADD(a,b) make_float2((a).x+(b).x, (a).y+(b).y)

#define C16_1 0.92387953251128675613f
#define S16_1 0.38268343236508977173f
#define RS2   0.70710678118654752440f

__device__ __forceinline__ void fft16_stage1(float2 r[16]) {
    BF1(r[0], r[8]);
    BFW(r[1], r[9],  C16_1, -S16_1);
    BFW(r[2], r[10], RS2,   -RS2);
    BFW(r[3], r[11], S16_1, -C16_1);
    BFI(r[4], r[12]);
    BFW(r[5], r[13], -S16_1, -C16_1);
    BFW(r[6], r[14], -RS2,   -RS2);
    BFW(r[7], r[15], -C16_1, -S16_1);
}
// stage1 with r[8..15] implicitly zero
__device__ __forceinline__ void fft16_stage1_p8(float2 r[16]) {
    r[8]  = r[0];
    r[9]  = cmulc(r[1],  C16_1, -S16_1);
    r[10] = cmulc(r[2],  RS2,   -RS2);
    r[11] = cmulc(r[3],  S16_1, -C16_1);
    r[12] = make_float2(r[4].y, -r[4].x);
    r[13] = cmulc(r[5], -S16_1, -C16_1);
    r[14] = cmulc(r[6], -RS2,   -RS2);
    r[15] = cmulc(r[7], -C16_1, -S16_1);
}
// stages 1+2 with only r[0..3] nonzero:
// r[j+4]=r[j]*W8^j, r[j+8]=r[j]*W16^j, r[j+12]=r[j]*W16^(3j)
__device__ __forceinline__ void fft16_stage12_p4(float2 r[16]) {
    r[4]  = r[0];
    r[5]  = cmulc(r[1],  RS2,   -RS2);
    r[6]  = make_float2(r[2].y, -r[2].x);
    r[7]  = cmulc(r[3], -RS2,   -RS2);
    r[8]  = r[0];
    r[9]  = cmulc(r[1],  C16_1, -S16_1);
    r[10] = cmulc(r[2],  RS2,   -RS2);
    r[11] = cmulc(r[3],  S16_1, -C16_1);
    r[12] = r[0];
    r[13] = cmulc(r[1],  S16_1, -C16_1);
    r[14] = cmulc(r[2], -RS2,   -RS2);
    r[15] = cmulc(r[3], -C16_1,  S16_1);
}
__device__ __forceinline__ void fft16_stage2(float2 r[16]) {
    BF1(r[0], r[4]);  BFW(r[1], r[5],  RS2, -RS2); BFI(r[2], r[6]);  BFW(r[3], r[7],  -RS2, -RS2);
    BF1(r[8], r[12]); BFW(r[9], r[13], RS2, -RS2); BFI(r[10],r[14]); BFW(r[11],r[15], -RS2, -RS2);
}
__device__ __forceinline__ void fft16_stage3(float2 r[16]) {
    BF1(r[0], r[2]);  BFI(r[1], r[3]);
    BF1(r[4], r[6]);  BFI(r[5], r[7]);
    BF1(r[8], r[10]); BFI(r[9], r[11]);
    BF1(r[12],r[14]); BFI(r[13],r[15]);
}
__device__ __forceinline__ void fft16_last_full(float2 r[16]) {
    BF1(r[0], r[1]);  BF1(r[2], r[3]);  BF1(r[4], r[5]);  BF1(r[6], r[7]);
    BF1(r[8], r[9]);  BF1(r[10],r[11]); BF1(r[12],r[13]); BF1(r[14],r[15]);
    SW(r[1], r[8]); SW(r[2], r[4]); SW(r[3], r[12]);
    SW(r[5], r[10]); SW(r[7], r[14]); SW(r[11], r[13]);
}
// last stage, only natural outputs 0..7 (sums)
__device__ __forceinline__ void fft16_last_half(float2 r[16]) {
    float2 s0 = CADD(r[0], r[1]);
    float2 s1 = CADD(r[2], r[3]);
    float2 s2 = CADD(r[4], r[5]);
    float2 s3 = CADD(r[6], r[7]);
    float2 s4 = CADD(r[8], r[9]);
    float2 s5 = CADD(r[10],r[11]);
    float2 s6 = CADD(r[12],r[13]);
    float2 s7 = CADD(r[14],r[15]);
    r[0]=s0; r[1]=s4; r[2]=s2; r[3]=s6; r[4]=s1; r[5]=s5; r[6]=s3; r[7]=s7;
}

// 256-pt FFT, 16x16 two-pass, warp-local sync only.
// PR: 0=dense, 1=inputs r[8..15]==0, 2=inputs r[4..15]==0.
// HALF: only outputs X[t+16*k2], k2<8.
template<int PR, bool HALF>
__device__ __forceinline__ void fft256_2pass(float2 r[16], int t, float2* Tb,
                                             const float2* tw) {
    if (PR == 2)      { fft16_stage12_p4(r); }
    else if (PR == 1) { fft16_stage1_p8(r); fft16_stage2(r); }
    else              { fft16_stage1(r);    fft16_stage2(r); }
    fft16_stage3(r);
    fft16_last_full(r);
    if (t) {
#pragma unroll
        for (int k1 = 1; k1 < 16; k1++) r[k1] = cmul(r[k1], tw[t * k1]);
    }
    __syncwarp();
#pragma unroll
    for (int k1 = 0; k1 < 16; k1++) Tb[k1 * 17 + t] = r[k1];
    __syncwarp();
#pragma unroll
    for (int n2 = 0; n2 < 16; n2++) r[n2] = Tb[t * 17 + n2];
    fft16_stage1(r);
    fft16_stage2(r);
    fft16_stage3(r);
    if (HALF) fft16_last_half(r); else fft16_last_full(r);
}

__device__ __forceinline__ void init_tw256(float2* tw) {
    int i = threadIdx.x;
    if (i < 256) {
        float sn, cs;
        sincospif((float)i / 128.0f, &sn, &cs);
        tw[i] = make_float2(cs, -sn);
    }
}

__device__ __forceinline__ float2 shfl2(float2 v, int src, unsigned mask) {
    float2 r;
    r.x = __shfl_sync(mask, v.x, src, 32);
    r.y = __shfl_sync(mask, v.y, src, 32);
    return r;
}

// ---------------------------------------------------------------------------
// Fused kernel-filter prep: one block per channel. 512 threads, 32 FFT slots.
// Smem (float2): Skf[64*129] | pool[32*272] | tw[256]
#define KF_POOL  8256
#define KF_TW    16960
#define KF_F2    17216
#define KF_SMEM_BYTES (KF_F2 * 8)

__global__ __launch_bounds__(512)
void kf_fused_kernel(const float* __restrict__ kin) {
    extern __shared__ float2 dyn[];
    float2* Skf  = dyn;
    float2* pool = dyn + KF_POOL;
    float2* tw   = dyn + KF_TW;

    const int tid  = threadIdx.x;
    const int c    = blockIdx.x;
    const int cb   = tid >> 4;
    const int t    = tid & 15;
    const int lane = tid & 31;
    const int srcl = (lane & 16) | ((16 - t) & 15);
    float2* Tb = pool + cb * 272;

    init_tw256(tw);
    __syncthreads();

    // Phase A: 32 packed row-pair FFTs of the 64x64 real kernel
    {
        int rA = 2 * cb, rB = rA + 1;
        const float* kA = kin + ((size_t)c * KH + rA) * KW;
        float2 r[16];
#pragma unroll
        for (int n1 = 0; n1 < 4; n1++) {
            int idx = 16 * n1 + t;
            r[n1] = make_float2(kA[idx], kA[KW + idx]);
        }
        fft256_2pass<2, false>(r, t, Tb, tw);
#pragma unroll
        for (int k2 = 0; k2 <= 8; k2++) {
            float2 p1 = shfl2(r[(15 - k2) & 15], srcl, 0xffffffffu);
            float2 Zm = (t == 0) ? r[(16 - k2) & 15] : p1;
            Zm.y = -Zm.y;
            float2 Z = r[k2 & 15];
            float2 A = make_float2(0.5f * (Z.x + Zm.x), 0.5f * (Z.y + Zm.y));
            float2 d = make_float2(Z.x - Zm.x, Z.y - Zm.y);
            float2 B = make_float2(0.5f * d.y, -0.5f * d.x);
            int k = t + 16 * k2;
            if (k <= 128) {
                Skf[rA * 129 + k] = A;
                Skf[rB * 129 + k] = B;
            }
        }
    }
    __syncthreads();

    // Phase B: column FFTs (129 cols as 128 slots; slot 0 packs cols {0,128})
#pragma unroll 1
    for (int g = 0; g < 4; g++) {
        int cidx = g * 32 + cb;
        float2 r[16];
        if (cidx == 0) {
#pragma unroll
            for (int n1 = 0; n1 < 4; n1++) {
                int row = 16 * n1 + t;
                r[n1] = make_float2(Skf[row * 129].x, Skf[row * 129 + 128].x);
            }
        } else {
#pragma unroll
            for (int n1 = 0; n1 < 4; n1++)
                r[n1] = Skf[(16 * n1 + t) * 129 + cidx];
        }
        fft256_2pass<2, false>(r, t, Tb, tw);
        if (cidx == 0) {
            float2* K0 = g_kf + (size_t)c * NHF * NF;
            float2* K1 = g_kf + ((size_t)c * NHF + 128) * NF;
#pragma unroll
            for (int k2 = 0; k2 < 16; k2++) {
                float2 p1 = shfl2(r[15 - k2], srcl, 0x0000ffffu);
                float2 Zm = (t == 0) ? r[(16 - k2) & 15] : p1;
                Zm.y = -Zm.y;
                float2 Z = r[k2];
                float2 A = make_float2(0.5f * (Z.x + Zm.x), 0.5f * (Z.y + Zm.y));
                float2 d = make_float2(Z.x - Zm.x, Z.y - Zm.y);
                float2 B = make_float2(0.5f * d.y, -0.5f * d.x);
                int k = t + 16 * k2;
                K0[k] = A;
                K1[k] = B;
            }
        } else {
            float2* dst = g_kf + ((size_t)c * NHF + cidx) * NF;
#pragma unroll
            for (int k2 = 0; k2 < 16; k2++) dst[t + 16 * k2] = r[k2];
        }
    }
}

// ---------------------------------------------------------------------------
// Fused per-image kernel. 512 threads, 3 block barriers.
// Smem (float2): S[128*129] | pool[32*272] | tw[256]
#define SM_POOL  16512
#define SM_TW    25216
#define SM_F2    25472
#define SMEM_BYTES (SM_F2 * 8)

__global__ __launch_bounds__(512)
void conv2d_fused_kernel(const float* __restrict__ u,
                         const float* __restrict__ pre,
                         const float* __restrict__ post,
                         float* __restrict__ out) {
    extern __shared__ float2 dyn[];
    float2* S    = dyn;
    float2* pool = dyn + SM_POOL;
    float2* tw   = dyn + SM_TW;

    const int tid  = threadIdx.x;
    // c-major remap: blocks 4c..4c+3 (same channel, 4 batch images) run
    // concurrently -> their g_kf reads L2-dedup.
    const int c    = blockIdx.x >> 2;
    const int b    = blockIdx.x & 3;
    const int img  = b * N_CH + c;
    const int cb   = tid >> 4;
    const int t    = tid & 15;
    const int lane = tid & 31;
    const int srcl = (lane & 16) | ((16 - t) & 15);
    const size_t ibase = (size_t)img * (HH * WW);

    init_tw256(tw);
    float2* Tb = pool + cb * 272;
    __syncthreads();

    // -------- Phase 1: forward row FFTs, row pairs packed (warp-private) ---
#pragma unroll 1
    for (int it = 0; it < 2; it++) {
        int p = it * 32 + cb;
        int rA = 2 * p, rB = rA + 1;
        const float* uA = u   + ibase + (size_t)rA * WW;
        const float* pA = pre + ibase + (size_t)rA * WW;
        float2 r[16];
#pragma unroll
        for (int n1 = 0; n1 < 8; n1++) {
            int idx = 16 * n1 + t;
            r[n1] = make_float2(uA[idx] * pA[idx],
                                uA[WW + idx] * pA[WW + idx]);
        }
        fft256_2pass<1, false>(r, t, Tb, tw);
#pragma unroll
        for (int k2 = 0; k2 <= 8; k2++) {
            float2 p1 = shfl2(r[(15 - k2) & 15], srcl, 0xffffffffu);
            float2 Zm = (t == 0) ? r[(16 - k2) & 15] : p1;
            Zm.y = -Zm.y;
            float2 Z = r[k2 & 15];
            float2 A = make_float2(0.5f * (Z.x + Zm.x), 0.5f * (Z.y + Zm.y));
            float2 d = make_float2(Z.x - Zm.x, Z.y - Zm.y);
            float2 B = make_float2(0.5f * d.y, -0.5f * d.x);
            int k = t + 16 * k2;
            if (k <= 128) {
                S[rA * 129 + k] = A;
                S[rB * 129 + k] = B;
            }
        }
    }
    __syncthreads();

    // -------- Phase 2: column conv, columns warp-private -------------------
#pragma unroll 1
    for (int g = 0; g < 4; g++) {
        int cidx = g * 32 + cb;
        float2 r[16];
        float2 kreg[16];
        if (cidx != 0) {      // preload filter spectrum: hides L2 latency
            const float2* kfc = g_kf + ((size_t)c * NHF + cidx) * NF;
#pragma unroll
            for (int k2 = 0; k2 < 16; k2++) kreg[k2] = kfc[t + 16 * k2];
        }
        if (cidx == 0) {      // packed pair {col 0, col 128}
#pragma unroll
            for (int n1 = 0; n1 < 8; n1++) {
                int row = 16 * n1 + t;
                r[n1] = make_float2(S[row * 129].x, S[row * 129 + 128].x);
            }
        } else {
#pragma unroll
            for (int n1 = 0; n1 < 8; n1++)
                r[n1] = S[(16 * n1 + t) * 129 + cidx];
        }
        fft256_2pass<1, false>(r, t, Tb, tw);

        if (cidx == 0) {
            const float2* KA = g_kf + (size_t)c * NHF * NF;
            const float2* KB = g_kf + ((size_t)c * NHF + 128) * NF;
            float2 rn[16];
#pragma unroll
            for (int k2 = 0; k2 < 16; k2++) {
                float2 p1 = shfl2(r[15 - k2], srcl, 0x0000ffffu);
                float2 Zm = (t == 0) ? r[(16 - k2) & 15] : p1;
                Zm.y = -Zm.y;
                float2 Z = r[k2];
                float2 A = make_float2(0.5f * (Z.x + Zm.x), 0.5f * (Z.y + Zm.y));
                float2 d = make_float2(Z.x - Zm.x, Z.y - Zm.y);
                float2 B = make_float2(0.5f * d.y, -0.5f * d.x);
                int k = t + 16 * k2;
                float2 YA = cmul(A, KA[k]);
                float2 YB = cmul(B, KB[k]);
                rn[k2] = make_float2(YA.x - YB.y, YA.y + YB.x);
            }
#pragma unroll
            for (int k2 = 0; k2 < 16; k2++) r[k2] = rn[k2];
        } else {
#pragma unroll
            for (int k2 = 0; k2 < 16; k2++)
                r[k2] = cmul(r[k2], kreg[k2]);
        }
        // inverse = conj -> fwd(half-output) -> conj
#pragma unroll
        for (int k2 = 0; k2 < 16; k2++) r[k2].y = -r[k2].y;
        fft256_2pass<0, true>(r, t, Tb, tw);
        if (cidx == 0) {
#pragma unroll
            for (int m = 0; m < 8; m++) {
                int n = t + 16 * m;
                S[n * 129]       = make_float2(r[m].x, 0.0f);
                S[n * 129 + 128] = make_float2(-r[m].y, 0.0f);
            }
        } else {
#pragma unroll
            for (int m = 0; m < 8; m++) {
                int n = t + 16 * m;
                S[n * 129 + cidx] = make_float2(r[m].x, -r[m].y);
            }
        }
    }
    __syncthreads();

    // -------- Phase 3: inverse row FFTs, row pairs packed (warp-private) ---
    const float scale = 1.0f / 65536.0f;
#pragma unroll 1
    for (int it = 0; it < 2; it++) {
        int p = it * 32 + cb;
        int rA = 2 * p, rB = rA + 1;
        float2 r[16];
#pragma unroll
        for (int n1 = 0; n1 < 16; n1++) {
            int idx = 16 * n1 + t;
            float2 YA, YB;
            if (idx <= 128) {
                YA = S[rA * 129 + idx];
                YB = S[rB * 129 + idx];
            } else {
                int m2 = 256 - idx;
                float2 a = S[rA * 129 + m2];
                float2 b2 = S[rB * 129 + m2];
                YA = make_float2(a.x, -a.y);
                YB = make_float2(b2.x, -b2.y);
            }
            r[n1] = make_float2(YA.x - YB.y, -(YA.y + YB.x));
        }
        fft256_2pass<0, true>(r, t, Tb, tw);
        size_t oA = ibase + (size_t)rA * WW;
        size_t oB = oA + WW;
#pragma unroll
        for (int m = 0; m < 8; m++) {
            int n = t + 16 * m;
            out[oA + n] =  r[m].x * scale * post[oA + n];
            out[oB + n] = -r[m].y * scale * post[oB + n];
        }
    }
}

// ---------------------------------------------------------------------------
extern "C" void kernel_launch(void* const* d_in, const int* in_sizes, int n_in,
                              void* d_out, int out_size) {
    const float* u    = (const float*)d_in[0];
    const float* k    = (const float*)d_in[1];
    const float* pre  = (const float*)d_in[2];
    const float* post = (const float*)d_in[3];
    float* out = (float*)d_out;

    cudaFuncSetAttribute(kf_fused_kernel,
                         cudaFuncAttributeMaxDynamicSharedMemorySize, KF_SMEM_BYTES);
    cudaFuncSetAttribute(conv2d_fused_kernel,
                         cudaFuncAttributeMaxDynamicSharedMemorySize, SMEM_BYTES);

    kf_fused_kernel<<<N_CH, 512, KF_SMEM_BYTES>>>(k);
    conv2d_fused_kernel<<<N_IMG, 512, SMEM_BYTES>>>(u, pre, post, out);
}

// round 6
// speedup vs baseline: 4.6349x; 1.1432x over previous
#include <cuda_runtime.h>

// u, pregate, postgate: (4,256,128,128) f32 ; k: (256,64,64) f32
// y = postgate * irfft2( rfft2(u*pregate,256x256) * rfft2(k,256x256) )[:128,:128]

#define N_IMG   1024
#define N_CH    256
#define HH      128
#define WW      128
#define KH      64
#define KW      64
#define NF      256
#define NHF     129

__device__ float2 g_kf[(size_t)N_CH * NHF * NF];    // [c][col][k]

__device__ __forceinline__ float2 cmul(float2 a, float2 b) {
    return make_float2(a.x * b.x - a.y * b.y, a.x * b.y + a.y * b.x);
}
__device__ __forceinline__ float2 cmulc(float2 a, float wr, float wi) {
    return make_float2(a.x * wr - a.y * wi, a.x * wi + a.y * wr);
}

#define BF1(a,b) { float ax=a.x, ay=a.y; a.x=ax+b.x; a.y=ay+b.y; b.x=ax-b.x; b.y=ay-b.y; }
#define BFI(a,b) { float ax=a.x, ay=a.y; float dx=ax-b.x, dy=ay-b.y; a.x=ax+b.x; a.y=ay+b.y; b.x=dy; b.y=-dx; }
#define BFW(a,b,wr,wi) { float ax=a.x, ay=a.y; float dx=ax-b.x, dy=ay-b.y; \
    a.x=ax+b.x; a.y=ay+b.y; b.x=dx*(wr)-dy*(wi); b.y=dx*(wi)+dy*(wr); }
#define SW(a,b) { float2 _t=a; a=b; b=_t; }
#define CADD(a,b) make_float2((a).x+(b).x, (a).y+(b).y)

#define C16_1 0.92387953251128675613f
#define S16_1 0.38268343236508977173f
#define RS2   0.70710678118654752440f

__device__ __forceinline__ void fft16_stage1(float2 r[16]) {
    BF1(r[0], r[8]);
    BFW(r[1], r[9],  C16_1, -S16_1);
    BFW(r[2], r[10], RS2,   -RS2);
    BFW(r[3], r[11], S16_1, -C16_1);
    BFI(r[4], r[12]);
    BFW(r[5], r[13], -S16_1, -C16_1);
    BFW(r[6], r[14], -RS2,   -RS2);
    BFW(r[7], r[15], -C16_1, -S16_1);
}
__device__ __forceinline__ void fft16_stage1_p8(float2 r[16]) {
    r[8]  = r[0];
    r[9]  = cmulc(r[1],  C16_1, -S16_1);
    r[10] = cmulc(r[2],  RS2,   -RS2);
    r[11] = cmulc(r[3],  S16_1, -C16_1);
    r[12] = make_float2(r[4].y, -r[4].x);
    r[13] = cmulc(r[5], -S16_1, -C16_1);
    r[14] = cmulc(r[6], -RS2,   -RS2);
    r[15] = cmulc(r[7], -C16_1, -S16_1);
}
__device__ __forceinline__ void fft16_stage12_p4(float2 r[16]) {
    r[4]  = r[0];
    r[5]  = cmulc(r[1],  RS2,   -RS2);
    r[6]  = make_float2(r[2].y, -r[2].x);
    r[7]  = cmulc(r[3], -RS2,   -RS2);
    r[8]  = r[0];
    r[9]  = cmulc(r[1],  C16_1, -S16_1);
    r[10] = cmulc(r[2],  RS2,   -RS2);
    r[11] = cmulc(r[3],  S16_1, -C16_1);
    r[12] = r[0];
    r[13] = cmulc(r[1],  S16_1, -C16_1);
    r[14] = cmulc(r[2], -RS2,   -RS2);
    r[15] = cmulc(r[3], -C16_1,  S16_1);
}
__device__ __forceinline__ void fft16_stage2(float2 r[16]) {
    BF1(r[0], r[4]);  BFW(r[1], r[5],  RS2, -RS2); BFI(r[2], r[6]);  BFW(r[3], r[7],  -RS2, -RS2);
    BF1(r[8], r[12]); BFW(r[9], r[13], RS2, -RS2); BFI(r[10],r[14]); BFW(r[11],r[15], -RS2, -RS2);
}
__device__ __forceinline__ void fft16_stage3(float2 r[16]) {
    BF1(r[0], r[2]);  BFI(r[1], r[3]);
    BF1(r[4], r[6]);  BFI(r[5], r[7]);
    BF1(r[8], r[10]); BFI(r[9], r[11]);
    BF1(r[12],r[14]); BFI(r[13],r[15]);
}
__device__ __forceinline__ void fft16_last_full(float2 r[16]) {
    BF1(r[0], r[1]);  BF1(r[2], r[3]);  BF1(r[4], r[5]);  BF1(r[6], r[7]);
    BF1(r[8], r[9]);  BF1(r[10],r[11]); BF1(r[12],r[13]); BF1(r[14],r[15]);
    SW(r[1], r[8]); SW(r[2], r[4]); SW(r[3], r[12]);
    SW(r[5], r[10]); SW(r[7], r[14]); SW(r[11], r[13]);
}
__device__ __forceinline__ void fft16_last_half(float2 r[16]) {
    float2 s0 = CADD(r[0], r[1]);
    float2 s1 = CADD(r[2], r[3]);
    float2 s2 = CADD(r[4], r[5]);
    float2 s3 = CADD(r[6], r[7]);
    float2 s4 = CADD(r[8], r[9]);
    float2 s5 = CADD(r[10],r[11]);
    float2 s6 = CADD(r[12],r[13]);
    float2 s7 = CADD(r[14],r[15]);
    r[0]=s0; r[1]=s4; r[2]=s2; r[3]=s6; r[4]=s1; r[5]=s5; r[6]=s3; r[7]=s7;
}

// 256-pt FFT, 16x16 two-pass, warp-local sync only.
// PR: 0=dense, 1=inputs r[8..15]==0, 2=inputs r[4..15]==0.
// HALF: only outputs X[t+16*k2], k2<8.
// Tb: per-half-warp 16x18 float2 slot (pitch 18 -> float4-clean + conflict-free).
// twp: permuted twiddle table twp[t*17+k1] = exp(-2*pi*i*t*k1/256) (conflict-free).
template<int PR, bool HALF>
__device__ __forceinline__ void fft256_2pass(float2 r[16], int t, float2* Tb,
                                             const float2* twp) {
    if (PR == 2)      { fft16_stage12_p4(r); }
    else if (PR == 1) { fft16_stage1_p8(r); fft16_stage2(r); }
    else              { fft16_stage1(r);    fft16_stage2(r); }
    fft16_stage3(r);
    fft16_last_full(r);
    if (t) {
        const float2* twt = twp + t * 17;
#pragma unroll
        for (int k1 = 1; k1 < 16; k1++) r[k1] = cmul(r[k1], twt[k1]);
    }
    __syncwarp();
    // store row-contiguous as float4 pairs: Tb[t][k1] = r[k1]
    {
        float4* row = (float4*)(Tb + t * 18);
#pragma unroll
        for (int j = 0; j < 8; j++)
            row[j] = make_float4(r[2*j].x, r[2*j].y, r[2*j+1].x, r[2*j+1].y);
    }
    __syncwarp();
#pragma unroll
    for (int n2 = 0; n2 < 16; n2++) r[n2] = Tb[n2 * 18 + t];
    fft16_stage1(r);
    fft16_stage2(r);
    fft16_stage3(r);
    if (HALF) fft16_last_half(r); else fft16_last_full(r);
}

// permuted twiddle init: twp[t*17+k1]
__device__ __forceinline__ void init_twp(float2* twp) {
    for (int i = threadIdx.x; i < 272; i += blockDim.x) {
        int t = i / 17, k1 = i - t * 17;
        float sn, cs;
        sincospif((float)(t * k1) / 128.0f, &sn, &cs);
        twp[i] = make_float2(cs, -sn);
    }
}

__device__ __forceinline__ float2 shfl2(float2 v, int src, unsigned mask) {
    float2 r;
    r.x = __shfl_sync(mask, v.x, src, 32);
    r.y = __shfl_sync(mask, v.y, src, 32);
    return r;
}

// ---------------------------------------------------------------------------
// Fused kernel-filter prep: one block per channel. 512 threads, 32 FFT slots.
// Smem (float2): Skf[64*129]=8256 | pool[32*288]=9216 | twp[272]
#define KF_POOL  8256
#define KF_TW    (KF_POOL + 32 * 288)
#define KF_F2    (KF_TW + 272)
#define KF_SMEM_BYTES (KF_F2 * 8)

__global__ __launch_bounds__(512)
void kf_fused_kernel(const float* __restrict__ kin) {
    extern __shared__ float2 dyn[];
    float2* Skf  = dyn;
    float2* pool = dyn + KF_POOL;
    float2* twp  = dyn + KF_TW;

    const int tid  = threadIdx.x;
    const int c    = blockIdx.x;
    const int cb   = tid >> 4;
    const int t    = tid & 15;
    const int lane = tid & 31;
    const int srcl = (lane & 16) | ((16 - t) & 15);
    float2* Tb = pool + cb * 288;

    init_twp(twp);
    __syncthreads();

    // Phase A: 32 packed row-pair FFTs of the 64x64 real kernel
    {
        int rA = 2 * cb, rB = rA + 1;
        const float* kA = kin + ((size_t)c * KH + rA) * KW;
        float2 r[16];
#pragma unroll
        for (int n1 = 0; n1 < 4; n1++) {
            int idx = 16 * n1 + t;
            r[n1] = make_float2(kA[idx], kA[KW + idx]);
        }
        fft256_2pass<2, false>(r, t, Tb, twp);
#pragma unroll
        for (int k2 = 0; k2 <= 8; k2++) {
            float2 p1 = shfl2(r[(15 - k2) & 15], srcl, 0xffffffffu);
            float2 Zm = (t == 0) ? r[(16 - k2) & 15] : p1;
            Zm.y = -Zm.y;
            float2 Z = r[k2 & 15];
            float2 A = make_float2(0.5f * (Z.x + Zm.x), 0.5f * (Z.y + Zm.y));
            float2 d = make_float2(Z.x - Zm.x, Z.y - Zm.y);
            float2 B = make_float2(0.5f * d.y, -0.5f * d.x);
            int k = t + 16 * k2;
            if (k <= 128) {
                Skf[rA * 129 + k] = A;
                Skf[rB * 129 + k] = B;
            }
        }
    }
    __syncthreads();

    // Phase B: column FFTs (129 cols as 128 slots; slot 0 packs cols {0,128})
#pragma unroll 1
    for (int g = 0; g < 4; g++) {
        int cidx = g * 32 + cb;
        float2 r[16];
        if (cidx == 0) {
#pragma unroll
            for (int n1 = 0; n1 < 4; n1++) {
                int row = 16 * n1 + t;
                r[n1] = make_float2(Skf[row * 129].x, Skf[row * 129 + 128].x);
            }
        } else {
#pragma unroll
            for (int n1 = 0; n1 < 4; n1++)
                r[n1] = Skf[(16 * n1 + t) * 129 + cidx];
        }
        fft256_2pass<2, false>(r, t, Tb, twp);
        if (cidx == 0) {
            float2* K0 = g_kf + (size_t)c * NHF * NF;
            float2* K1 = g_kf + ((size_t)c * NHF + 128) * NF;
#pragma unroll
            for (int k2 = 0; k2 < 16; k2++) {
                float2 p1 = shfl2(r[15 - k2], srcl, 0x0000ffffu);
                float2 Zm = (t == 0) ? r[(16 - k2) & 15] : p1;
                Zm.y = -Zm.y;
                float2 Z = r[k2];
                float2 A = make_float2(0.5f * (Z.x + Zm.x), 0.5f * (Z.y + Zm.y));
                float2 d = make_float2(Z.x - Zm.x, Z.y - Zm.y);
                float2 B = make_float2(0.5f * d.y, -0.5f * d.x);
                int k = t + 16 * k2;
                K0[k] = A;
                K1[k] = B;
            }
        } else {
            float2* dst = g_kf + ((size_t)c * NHF + cidx) * NF;
#pragma unroll
            for (int k2 = 0; k2 < 16; k2++) dst[t + 16 * k2] = r[k2];
        }
    }
}

// ---------------------------------------------------------------------------
// Fused per-image kernel. 512 threads, 3 block barriers.
// Smem (float2): S[128*129]=16512 | pool[32*288]=9216 | twp[272]
#define SM_POOL  16512
#define SM_TW    (SM_POOL + 32 * 288)
#define SM_F2    (SM_TW + 272)
#define SMEM_BYTES (SM_F2 * 8)

__global__ __launch_bounds__(512)
void conv2d_fused_kernel(const float* __restrict__ u,
                         const float* __restrict__ pre,
                         const float* __restrict__ post,
                         float* __restrict__ out) {
    extern __shared__ float2 dyn[];
    float2* S    = dyn;
    float2* pool = dyn + SM_POOL;
    float2* twp  = dyn + SM_TW;

    const int tid  = threadIdx.x;
    // c-major remap: blocks 4c..4c+3 (same channel) run concurrently -> g_kf L2-dedup
    const int c    = blockIdx.x >> 2;
    const int b    = blockIdx.x & 3;
    const int img  = b * N_CH + c;
    const int cb   = tid >> 4;
    const int t    = tid & 15;
    const int lane = tid & 31;
    const int srcl = (lane & 16) | ((16 - t) & 15);
    const size_t ibase = (size_t)img * (HH * WW);

    init_twp(twp);
    float2* Tb = pool + cb * 288;
    __syncthreads();

    // -------- Phase 1: forward row FFTs, row pairs packed (warp-private) ---
#pragma unroll 1
    for (int it = 0; it < 2; it++) {
        int p = it * 32 + cb;
        int rA = 2 * p, rB = rA + 1;
        const float* uA = u   + ibase + (size_t)rA * WW;
        const float* pA = pre + ibase + (size_t)rA * WW;
        float2 r[16];
#pragma unroll
        for (int n1 = 0; n1 < 8; n1++) {
            int idx = 16 * n1 + t;
            r[n1] = make_float2(uA[idx] * pA[idx],
                                uA[WW + idx] * pA[WW + idx]);
        }
        fft256_2pass<1, false>(r, t, Tb, twp);
#pragma unroll
        for (int k2 = 0; k2 <= 8; k2++) {
            float2 p1 = shfl2(r[(15 - k2) & 15], srcl, 0xffffffffu);
            float2 Zm = (t == 0) ? r[(16 - k2) & 15] : p1;
            Zm.y = -Zm.y;
            float2 Z = r[k2 & 15];
            float2 A = make_float2(0.5f * (Z.x + Zm.x), 0.5f * (Z.y + Zm.y));
            float2 d = make_float2(Z.x - Zm.x, Z.y - Zm.y);
            float2 B = make_float2(0.5f * d.y, -0.5f * d.x);
            int k = t + 16 * k2;
            if (k <= 128) {
                S[rA * 129 + k] = A;
                S[rB * 129 + k] = B;
            }
        }
    }
    __syncthreads();

    // -------- Phase 2: column conv, columns warp-private --------------------
#pragma unroll 1
    for (int g = 0; g < 4; g++) {
        int cidx = g * 32 + cb;
        float2 r[16];
        float2 kreg[16];
        if (cidx != 0) {      // preload filter spectrum
            const float2* kfc = g_kf + ((size_t)c * NHF + cidx) * NF;
#pragma unroll
            for (int k2 = 0; k2 < 16; k2++) kreg[k2] = kfc[t + 16 * k2];
        }
        if (cidx == 0) {      // packed pair {col 0, col 128}
#pragma unroll
            for (int n1 = 0; n1 < 8; n1++) {
                int row = 16 * n1 + t;
                r[n1] = make_float2(S[row * 129].x, S[row * 129 + 128].x);
            }
        } else {
#pragma unroll
            for (int n1 = 0; n1 < 8; n1++)
                r[n1] = S[(16 * n1 + t) * 129 + cidx];
        }
        fft256_2pass<1, false>(r, t, Tb, twp);

        if (cidx == 0) {
            const float2* KA = g_kf + (size_t)c * NHF * NF;
            const float2* KB = g_kf + ((size_t)c * NHF + 128) * NF;
            float2 rn[16];
#pragma unroll
            for (int k2 = 0; k2 < 16; k2++) {
                float2 p1 = shfl2(r[15 - k2], srcl, 0x0000ffffu);
                float2 Zm = (t == 0) ? r[(16 - k2) & 15] : p1;
                Zm.y = -Zm.y;
                float2 Z = r[k2];
                float2 A = make_float2(0.5f * (Z.x + Zm.x), 0.5f * (Z.y + Zm.y));
                float2 d = make_float2(Z.x - Zm.x, Z.y - Zm.y);
                float2 B = make_float2(0.5f * d.y, -0.5f * d.x);
                int k = t + 16 * k2;
                float2 YA = cmul(A, KA[k]);
                float2 YB = cmul(B, KB[k]);
                rn[k2] = make_float2(YA.x - YB.y, YA.y + YB.x);
            }
#pragma unroll
            for (int k2 = 0; k2 < 16; k2++) r[k2] = rn[k2];
        } else {
#pragma unroll
            for (int k2 = 0; k2 < 16; k2++)
                r[k2] = cmul(r[k2], kreg[k2]);
        }
        // inverse = conj -> fwd(half-output) -> conj
#pragma unroll
        for (int k2 = 0; k2 < 16; k2++) r[k2].y = -r[k2].y;
        fft256_2pass<0, true>(r, t, Tb, twp);
        if (cidx == 0) {
#pragma unroll
            for (int m = 0; m < 8; m++) {
                int n = t + 16 * m;
                S[n * 129]       = make_float2(r[m].x, 0.0f);
                S[n * 129 + 128] = make_float2(-r[m].y, 0.0f);
            }
        } else {
#pragma unroll
            for (int m = 0; m < 8; m++) {
                int n = t + 16 * m;
                S[n * 129 + cidx] = make_float2(r[m].x, -r[m].y);
            }
        }
    }
    __syncthreads();

    // -------- Phase 3: inverse row FFTs, row pairs packed (warp-private) ---
    const float scale = 1.0f / 65536.0f;
#pragma unroll 1
    for (int it = 0; it < 2; it++) {
        int p = it * 32 + cb;
        int rA = 2 * p, rB = rA + 1;
        float2 r[16];
#pragma unroll
        for (int n1 = 0; n1 < 16; n1++) {
            int idx = 16 * n1 + t;
            float2 YA, YB;
            if (idx <= 128) {
                YA = S[rA * 129 + idx];
                YB = S[rB * 129 + idx];
            } else {
                int m2 = 256 - idx;
                float2 a  = S[rA * 129 + m2];
                float2 b2 = S[rB * 129 + m2];
                YA = make_float2(a.x, -a.y);
                YB = make_float2(b2.x, -b2.y);
            }
            r[n1] = make_float2(YA.x - YB.y, -(YA.y + YB.x));
        }
        fft256_2pass<0, true>(r, t, Tb, twp);
        size_t oA = ibase + (size_t)rA * WW;
        size_t oB = oA + WW;
#pragma unroll
        for (int m = 0; m < 8; m++) {
            int n = t + 16 * m;
            out[oA + n] =  r[m].x * scale * post[oA + n];
            out[oB + n] = -r[m].y * scale * post[oB + n];
        }
    }
}

// ---------------------------------------------------------------------------
extern "C" void kernel_launch(void* const* d_in, const int* in_sizes, int n_in,
                              void* d_out, int out_size) {
    const float* u    = (const float*)d_in[0];
    const float* k    = (const float*)d_in[1];
    const float* pre  = (const float*)d_in[2];
    const float* post = (const float*)d_in[3];
    float* out = (float*)d_out;

    cudaFuncSetAttribute(kf_fused_kernel,
                         cudaFuncAttributeMaxDynamicSharedMemorySize, KF_SMEM_BYTES);
    cudaFuncSetAttribute(conv2d_fused_kernel,
                         cudaFuncAttributeMaxDynamicSharedMemorySize, SMEM_BYTES);

    kf_fused_kernel<<<N_CH, 512, KF_SMEM_BYTES>>>(k);
    conv2d_fused_kernel<<<N_IMG, 512, SMEM_BYTES>>>(u, pre, post, out);
}